// round 17
// baseline (speedup 1.0000x reference)
#include <cuda_runtime.h>
#include <cuda_bf16.h>
#include <cstdint>
#include <cstddef>

// B=8, PH=PW=256, D=512, C=256, WS=8, NGRAM=2, HEADS=8, hd=32
// uni grid: 32x32 per image -> NPOS = 8*32*32 = 8192 positions
#define NPOS 8192

// Scratch (device globals; allocation is forbidden)
__device__ __align__(16) float g_wt[128 * 256];   // transposed conv weights [k][c]
__device__ __align__(16) float g_qkv[NPOS * 768]; // qkv per position [q|k|v] fp32
__device__ __align__(16) float g_biasf[512];      // fused bias

// bf16 split planes (hi/lo) for emulated-fp32 GEMM operands
__device__ __align__(16) __nv_bfloat16 g_uA_hi[NPOS * 256];  // uni (GEMM1 A)
__device__ __align__(16) __nv_bfloat16 g_uA_lo[NPOS * 256];
__device__ __align__(16) __nv_bfloat16 g_wq_hi[768 * 256];   // qkv_w (GEMM1 B)
__device__ __align__(16) __nv_bfloat16 g_wq_lo[768 * 256];
__device__ __align__(16) __nv_bfloat16 g_mf_hi[NPOS * 512];  // mfb (GEMM2 A)
__device__ __align__(16) __nv_bfloat16 g_mf_lo[NPOS * 512];
__device__ __align__(16) __nv_bfloat16 g_wc_hi[512 * 512];   // wcat (GEMM2 B)
__device__ __align__(16) __nv_bfloat16 g_wc_lo[512 * 512];

// ===========================================================================
// helpers
// ===========================================================================
__device__ __forceinline__ uint32_t smem_u32(const void* p) {
    uint32_t a;
    asm("{ .reg .u64 t; cvta.to.shared.u64 t, %1; cvt.u32.u64 %0, t; }"
        : "=r"(a) : "l"(p));
    return a;
}
__device__ __forceinline__ void cp_async16(uint32_t saddr, const void* g) {
    asm volatile("cp.async.cg.shared.global [%0], [%1], 16;" :: "r"(saddr), "l"(g));
}
__device__ __forceinline__ void cp_commit() {
    asm volatile("cp.async.commit_group;" ::: "memory");
}
__device__ __forceinline__ void cp_wait1() {
    asm volatile("cp.async.wait_group 1;" ::: "memory");
}
__device__ __forceinline__ void cp_wait0() {
    asm volatile("cp.async.wait_group 0;" ::: "memory");
}
// m16n8k16 bf16 MMA, fp32 accumulate
__device__ __forceinline__ void mma_bf16(float* c, const uint32_t* a, const uint32_t* b) {
    asm volatile(
        "mma.sync.aligned.m16n8k16.row.col.f32.bf16.bf16.f32 "
        "{%0,%1,%2,%3}, {%4,%5,%6,%7}, {%8,%9}, {%0,%1,%2,%3};"
        : "+f"(c[0]), "+f"(c[1]), "+f"(c[2]), "+f"(c[3])
        : "r"(a[0]), "r"(a[1]), "r"(a[2]), "r"(a[3]), "r"(b[0]), "r"(b[1]));
}
// ldmatrix: 4x (8x8 b16) tiles -> a0..a3 in mma order
__device__ __forceinline__ void ldsm_x4(uint32_t* r, uint32_t addr) {
    asm volatile("ldmatrix.sync.aligned.m8n8.x4.shared.b16 {%0,%1,%2,%3}, [%4];"
                 : "=r"(r[0]), "=r"(r[1]), "=r"(r[2]), "=r"(r[3]) : "r"(addr));
}
__device__ __forceinline__ void ldsm_x2(uint32_t* r, uint32_t addr) {
    asm volatile("ldmatrix.sync.aligned.m8n8.x2.shared.b16 {%0,%1}, [%2];"
                 : "=r"(r[0]), "=r"(r[1]) : "r"(addr));
}
__device__ __forceinline__ void split_bf16(float v, __nv_bfloat16* hi, __nv_bfloat16* lo) {
    __nv_bfloat16 h = __float2bfloat16(v);
    *hi = h;
    *lo = __float2bfloat16(v - __bfloat162float(h));
}
__device__ __forceinline__ uint32_t pack_bf16x2(__nv_bfloat16 a, __nv_bfloat16 b) {
    uint16_t lo_u = *reinterpret_cast<uint16_t*>(&a);
    uint16_t hi_u = *reinterpret_cast<uint16_t*>(&b);
    return (uint32_t)lo_u | ((uint32_t)hi_u << 16);
}

// ===========================================================================
// prep: ALL weight prep in one kernel, 256-thread blocks, grid 1152:
//   [0,128)     conv weight transpose
//   [128,896)   qkv_w bf16 split
//   [896,1152)  fuse proj+merge (2 d-rows per block) + fused bias
// ===========================================================================
__global__ __launch_bounds__(256) void prep_kernel(const float* __restrict__ uw,
                                                   const float* __restrict__ qkvw,
                                                   const float* __restrict__ mw,
                                                   const float* __restrict__ pw,
                                                   const float* __restrict__ pb,
                                                   const float* __restrict__ mb) {
    int blk = blockIdx.x;
    int t = threadIdx.x;
    if (blk < 128) {
        int idx = blk * 256 + t;
        int c = idx >> 7;
        int kk = idx & 127;
        g_wt[kk * 256 + c] = uw[idx];
    } else if (blk < 896) {
        int idx = (blk - 128) * 256 + t;  // 768*256 elems
        split_bf16(qkvw[idx], &g_wq_hi[idx], &g_wq_lo[idx]);
    } else {
        // fuse_w for d-rows d0, d0+1; thread t covers outputs e=t and e=256+t.
        int d0 = (blk - 896) * 2;
        const float* m0 = mw + d0 * 512;
        const float* m1 = m0 + 512;
        float a00 = 0.f, a01 = 0.f, a10 = 0.f, a11 = 0.f;
#pragma unroll 4
        for (int cc = 0; cc < 256; cc++) {
            float v = pw[cc * 256 + t];
            a00 += m0[cc] * v;
            a01 += m0[256 + cc] * v;
            a10 += m1[cc] * v;
            a11 += m1[256 + cc] * v;
        }
        split_bf16(a00, &g_wc_hi[d0 * 512 + t], &g_wc_lo[d0 * 512 + t]);
        split_bf16(a01, &g_wc_hi[d0 * 512 + 256 + t], &g_wc_lo[d0 * 512 + 256 + t]);
        split_bf16(a10, &g_wc_hi[(d0 + 1) * 512 + t], &g_wc_lo[(d0 + 1) * 512 + t]);
        split_bf16(a11, &g_wc_hi[(d0 + 1) * 512 + 256 + t],
                   &g_wc_lo[(d0 + 1) * 512 + 256 + t]);

        // fused bias for both d-rows
        __shared__ float red[2][8];
        float pv = pb[t];
        float b0 = pv * (m0[t] + m0[256 + t]);
        float b1 = pv * (m1[t] + m1[256 + t]);
#pragma unroll
        for (int sh = 16; sh >= 1; sh >>= 1) {
            b0 += __shfl_xor_sync(0xffffffffu, b0, sh);
            b1 += __shfl_xor_sync(0xffffffffu, b1, sh);
        }
        if ((t & 31) == 0) {
            red[0][t >> 5] = b0;
            red[1][t >> 5] = b1;
        }
        __syncthreads();
        if (t == 0) {
            float s0 = mb[d0], s1 = mb[d0 + 1];
#pragma unroll
            for (int i = 0; i < 8; i++) {
                s0 += red[0][i];
                s1 += red[1][i];
            }
            g_biasf[d0] = s0;
            g_biasf[d0 + 1] = s1;
        }
    }
}

// ===========================================================================
// Depthwise conv 8x8 stride 8 (VALID). 8 w-positions per block. At the HBM
// roofline (89% DRAM, 1.07GB input) — do not touch.
// ===========================================================================
__global__ __launch_bounds__(256) void conv_kernel(const float* __restrict__ x,
                                                   const float* __restrict__ ub) {
    int blk = blockIdx.x;
    int bb = blk >> 7;
    int h = (blk >> 2) & 31;
    int wg = blk & 3;
    int c = threadIdx.x;

    const float* xp =
        x + ((size_t)(bb * 256 + h * 8) * 256 + wg * 64) * 512 + 2 * c;

    float acc[8];
#pragma unroll
    for (int p = 0; p < 8; p++) acc[p] = 0.f;

#pragma unroll
    for (int kh = 0; kh < 8; kh++) {
#pragma unroll
        for (int kw = 0; kw < 8; kw++) {
            int kidx = kh * 8 + kw;
            float w0 = g_wt[kidx * 256 + c];
            float w1 = g_wt[(64 + kidx) * 256 + c];
            const float* row = xp + ((size_t)kh * 256 + kw) * 512;
#pragma unroll
            for (int p = 0; p < 8; p++) {
                float2 xv = *(const float2*)(row + (size_t)p * 8 * 512);
                acc[p] += xv.x * w0 + xv.y * w1;
            }
        }
    }

    float b = ub[c];
    int pos0 = (bb * 32 + h) * 32 + wg * 8;
#pragma unroll
    for (int p = 0; p < 8; p++) {
        int o = (pos0 + p) * 256 + c;
        split_bf16(acc[p] + b, &g_uA_hi[o], &g_uA_lo[o]);
    }
}

// ===========================================================================
// Emulated-fp32 NT GEMM via bf16x2 split (3 MMAs: hi*hi + hi*lo + lo*hi):
//   C[m][n] = sum_k A[m][k]*B[n][k] + bias[n]
// Template NTW = n-tiles (8 cols) per warp: CTA tile = 128 x (32*NTW).
//   NTW=4 -> 128x128 (GEMM2, 256 CTAs = 1 wave)
//   NTW=3 -> 128x96  (GEMM1, 512 CTAs = 2 fuller waves, less quantization)
// BK=32 double-buffered cp.async, 8 warps (2x4).
// ===========================================================================
#define PITCHB 80                       // bytes per row (64 data + 16 pad)
#define PLANE_B (128 * PITCHB)          // bytes per plane = 10240
#define BUF_B (4 * PLANE_B)             // bytes per buffer = 40960
#define TB_SMEM (2 * BUF_B)             // 81920 bytes

template <int NTW>
__global__ __launch_bounds__(256, 2) void bgemm_x2(const __nv_bfloat16* __restrict__ Ah,
                                                   const __nv_bfloat16* __restrict__ Al,
                                                   const __nv_bfloat16* __restrict__ Bh,
                                                   const __nv_bfloat16* __restrict__ Bl,
                                                   const float* __restrict__ bias,
                                                   float* __restrict__ C,
                                                   int K, int N) {
    constexpr int NCTA = 32 * NTW;  // CTA n-tile
    extern __shared__ __align__(16) uint32_t smemw[];
    uint32_t sbase = smem_u32(smemw);

    int tid = threadIdx.x;
    int wid = tid >> 5;
    int lane = tid & 31;
    int g = lane >> 2;      // 0..7
    int tg = lane & 3;      // 0..3
    int warp_m = wid >> 2;  // 0..1
    int warp_n = wid & 3;   // 0..3

    int bm = blockIdx.y * 128;
    int bn = blockIdx.x * NCTA;

    uint32_t laneA =
        (uint32_t)((((lane & 7) + ((lane >> 3) & 1) * 8) * PITCHB) + ((lane >> 4) & 1) * 16);
    uint32_t laneB = (uint32_t)(((lane & 7) * PITCHB) + ((lane >> 3) & 1) * 16);

    int row = tid >> 1;
    int half = tid & 1;
    bool doB = (row < NCTA);
    const __nv_bfloat16* gAh = Ah + (size_t)(bm + row) * K + half * 16;
    const __nv_bfloat16* gAl = Al + (size_t)(bm + row) * K + half * 16;
    const __nv_bfloat16* gBh = Bh + (size_t)(bn + (doB ? row : 0)) * K + half * 16;
    const __nv_bfloat16* gBl = Bl + (size_t)(bn + (doB ? row : 0)) * K + half * 16;
    uint32_t dst0 = sbase + (uint32_t)(row * PITCHB + half * 32);

    int nchunks = K >> 5;

#define LOAD_CHUNK(ci)                                                    \
    {                                                                     \
        uint32_t _o = ((ci) & 1) * BUF_B;                                 \
        int _k = (ci) * 32;                                               \
        cp_async16(dst0 + _o,                     gAh + _k);              \
        cp_async16(dst0 + _o + 16,                gAh + _k + 8);          \
        cp_async16(dst0 + _o + PLANE_B,           gAl + _k);              \
        cp_async16(dst0 + _o + PLANE_B + 16,      gAl + _k + 8);          \
        if (doB) {                                                        \
            cp_async16(dst0 + _o + 2 * PLANE_B,       gBh + _k);          \
            cp_async16(dst0 + _o + 2 * PLANE_B + 16,  gBh + _k + 8);      \
            cp_async16(dst0 + _o + 3 * PLANE_B,       gBl + _k);          \
            cp_async16(dst0 + _o + 3 * PLANE_B + 16,  gBl + _k + 8);      \
        }                                                                 \
        cp_commit();                                                      \
    }

    float c[4][NTW][4];
#pragma unroll
    for (int mt = 0; mt < 4; mt++)
#pragma unroll
        for (int nt = 0; nt < NTW; nt++)
#pragma unroll
            for (int e = 0; e < 4; e++) c[mt][nt][e] = 0.f;

    LOAD_CHUNK(0);

    for (int i = 0; i < nchunks; i++) {
        if (i + 1 < nchunks) {
            LOAD_CHUNK(i + 1);
            cp_wait1();
        } else {
            cp_wait0();
        }
        __syncthreads();

        uint32_t bufb = sbase + (uint32_t)(i & 1) * BUF_B;
        uint32_t abase = bufb + (uint32_t)(warp_m * 64) * PITCHB + laneA;
        uint32_t bbase = bufb + 2 * PLANE_B + (uint32_t)(warp_n * NTW * 8) * PITCHB + laneB;

#pragma unroll
        for (int ks = 0; ks < 2; ks++) {
            uint32_t kb = (uint32_t)ks * 32;
            uint32_t bh[NTW][2], bl[NTW][2];
#pragma unroll
            for (int nt = 0; nt < NTW; nt++) {
                uint32_t ba = bbase + (uint32_t)(nt * 8) * PITCHB + kb;
                ldsm_x2(bh[nt], ba);
                ldsm_x2(bl[nt], ba + PLANE_B);
            }
#pragma unroll
            for (int mt = 0; mt < 4; mt++) {
                uint32_t aa = abase + (uint32_t)(mt * 16) * PITCHB + kb;
                uint32_t ah[4], al[4];
                ldsm_x4(ah, aa);
                ldsm_x4(al, aa + PLANE_B);
#pragma unroll
                for (int nt = 0; nt < NTW; nt++) {
                    mma_bf16(c[mt][nt], ah, bh[nt]);   // hi*hi
                    mma_bf16(c[mt][nt], ah, bl[nt]);   // hi*lo
                    mma_bf16(c[mt][nt], al, bh[nt]);   // lo*hi
                }
            }
        }
        __syncthreads();
    }
#undef LOAD_CHUNK

    // epilogue: direct stores with bias
#pragma unroll
    for (int nt = 0; nt < NTW; nt++) {
        int col = bn + warp_n * (NTW * 8) + nt * 8 + 2 * tg;
        float2 bv = *(const float2*)(bias + col);
#pragma unroll
        for (int mt = 0; mt < 4; mt++) {
            int r0 = bm + warp_m * 64 + mt * 16 + g;
            float2 v0 = make_float2(c[mt][nt][0] + bv.x, c[mt][nt][1] + bv.y);
            float2 v1 = make_float2(c[mt][nt][2] + bv.x, c[mt][nt][3] + bv.y);
            *(float2*)(C + (size_t)r0 * N + col) = v0;
            *(float2*)(C + (size_t)(r0 + 8) * N + col) = v1;
        }
    }
}

// ===========================================================================
// Attention over the 2x2 token window, both contexts, with token-mean.
// 128 threads/block = 2 ctx x 8 heads x 8 lanes; 4 channels per thread.
// ===========================================================================
__global__ __launch_bounds__(128) void attn_kernel(const float* __restrict__ table) {
    int p = blockIdx.x;
    int bb = p >> 10;
    int h = (p >> 5) & 31;
    int w = p & 31;
    int tid = threadIdx.x;
    int ctx = tid >> 6;           // 0..1
    int head = (tid >> 3) & 7;    // 0..7
    int ln = tid & 7;             // 0..7 (4 channels each)

    int rows[2], cols[2];
    if (ctx == 0) {
        rows[0] = h;
        rows[1] = (h == 31) ? 30 : h + 1;
        cols[0] = w;
        cols[1] = (w == 31) ? 30 : w + 1;
    } else {
        rows[0] = (h == 0) ? 1 : h - 1;
        rows[1] = h;
        cols[0] = (w == 0) ? 1 : w - 1;
        cols[1] = w;
    }

    float4 q[4], k[4], v[4];
#pragma unroll
    for (int n = 0; n < 4; n++) {
        int tp = (bb * 32 + rows[n >> 1]) * 32 + cols[n & 1];
        const float* base = g_qkv + (size_t)tp * 768 + head * 32 + ln * 4;
        q[n] = *(const float4*)(base);
        k[n] = *(const float4*)(base + 256);
        v[n] = *(const float4*)(base + 512);
    }

    const float scale = 0.17677669529663687f;
    float s[4][4];
#pragma unroll
    for (int n = 0; n < 4; n++) {
#pragma unroll
        for (int m = 0; m < 4; m++) {
            float t = q[n].x * k[m].x + q[n].y * k[m].y +
                      q[n].z * k[m].z + q[n].w * k[m].w;
            t += __shfl_xor_sync(0xffffffffu, t, 4);
            t += __shfl_xor_sync(0xffffffffu, t, 2);
            t += __shfl_xor_sync(0xffffffffu, t, 1);
            int ridx = ((n >> 1) - (m >> 1) + 1) * 3 + ((n & 1) - (m & 1) + 1);
            s[n][m] = t * scale + table[ridx * 8 + head];
        }
    }

    float4 outd = make_float4(0.f, 0.f, 0.f, 0.f);
#pragma unroll
    for (int n = 0; n < 4; n++) {
        float mx = fmaxf(fmaxf(s[n][0], s[n][1]), fmaxf(s[n][2], s[n][3]));
        float e0 = __expf(s[n][0] - mx);
        float e1 = __expf(s[n][1] - mx);
        float e2 = __expf(s[n][2] - mx);
        float e3 = __expf(s[n][3] - mx);
        float inv = 1.f / (e0 + e1 + e2 + e3);
        outd.x += (e0 * v[0].x + e1 * v[1].x + e2 * v[2].x + e3 * v[3].x) * inv;
        outd.y += (e0 * v[0].y + e1 * v[1].y + e2 * v[2].y + e3 * v[3].y) * inv;
        outd.z += (e0 * v[0].z + e1 * v[1].z + e2 * v[2].z + e3 * v[3].z) * inv;
        outd.w += (e0 * v[0].w + e1 * v[1].w + e2 * v[2].w + e3 * v[3].w) * inv;
    }
    outd.x *= 0.25f; outd.y *= 0.25f; outd.z *= 0.25f; outd.w *= 0.25f;

    __nv_bfloat16 h0, l0, h1, l1, h2, l2, h3, l3;
    split_bf16(outd.x, &h0, &l0);
    split_bf16(outd.y, &h1, &l1);
    split_bf16(outd.z, &h2, &l2);
    split_bf16(outd.w, &h3, &l3);
    int o = p * 512 + ctx * 256 + head * 32 + ln * 4;
    uint2 hp = make_uint2(pack_bf16x2(h0, h1), pack_bf16x2(h2, h3));
    uint2 lp = make_uint2(pack_bf16x2(l0, l1), pack_bf16x2(l2, l3));
    *(uint2*)(g_mf_hi + o) = hp;
    *(uint2*)(g_mf_lo + o) = lp;
}

// ===========================================================================
// Launch. 5 launches: prep -> conv -> GEMM1(NTW=3) -> attn(profiled) -> GEMM2.
// ===========================================================================
extern "C" void kernel_launch(void* const* d_in, const int* in_sizes, int n_in,
                              void* d_out, int out_size) {
    const float* x     = (const float*)d_in[0];
    const float* uw    = (const float*)d_in[1];
    const float* ub    = (const float*)d_in[2];
    const float* qkvw  = (const float*)d_in[3];
    const float* qkvb  = (const float*)d_in[4];
    const float* table = (const float*)d_in[5];
    const float* pw    = (const float*)d_in[6];
    const float* pb    = (const float*)d_in[7];
    const float* mw    = (const float*)d_in[8];
    const float* mb    = (const float*)d_in[9];
    float* out = (float*)d_out;

    float* qkv;
    float* biasf;
    __nv_bfloat16 *uAh, *uAl, *wqh, *wql, *mfh, *mfl, *wch, *wcl;
    cudaGetSymbolAddress((void**)&qkv, g_qkv);
    cudaGetSymbolAddress((void**)&biasf, g_biasf);
    cudaGetSymbolAddress((void**)&uAh, g_uA_hi);
    cudaGetSymbolAddress((void**)&uAl, g_uA_lo);
    cudaGetSymbolAddress((void**)&wqh, g_wq_hi);
    cudaGetSymbolAddress((void**)&wql, g_wq_lo);
    cudaGetSymbolAddress((void**)&mfh, g_mf_hi);
    cudaGetSymbolAddress((void**)&mfl, g_mf_lo);
    cudaGetSymbolAddress((void**)&wch, g_wc_hi);
    cudaGetSymbolAddress((void**)&wcl, g_wc_lo);

    cudaFuncSetAttribute(bgemm_x2<3>, cudaFuncAttributeMaxDynamicSharedMemorySize,
                         TB_SMEM);
    cudaFuncSetAttribute(bgemm_x2<4>, cudaFuncAttributeMaxDynamicSharedMemorySize,
                         TB_SMEM);

    // 1: all weight prep
    prep_kernel<<<1152, 256>>>(uw, qkvw, mw, pw, pb, mb);
    // 2: conv (HBM roofline)
    conv_kernel<<<1024, 256>>>(x, ub);
    // 3: GEMM1 (128x96 tiles: 512 CTAs, better wave packing)
    bgemm_x2<3><<<dim3(768 / 96, 8192 / 128), 256, TB_SMEM>>>(uAh, uAl, wqh, wql,
                                                              qkvb, qkv, 256, 768);
    // 4: attention  <-- profiled slot (sanity: ~22.7us)
    attn_kernel<<<8192, 128>>>(table);
    // 5: GEMM2 (128x128 tiles: 256 CTAs = 1 wave)
    bgemm_x2<4><<<dim3(512 / 128, 8192 / 128), 256, TB_SMEM>>>(mfh, mfl, wch, wcl,
                                                               biasf, out, 512, 512);
}